// round 1
// baseline (speedup 1.0000x reference)
#include <cuda_runtime.h>
#include <math.h>

#define BATCH   2
#define SEQ     2048
#define DMODEL  1024
#define NHEADS  16
#define HDIM    64
#define WIN     64
#define MTOT    (BATCH*SEQ)   // 4096

// -------- scratch (static device globals; no allocation allowed) --------
__device__ float g_q[MTOT*DMODEL];
__device__ float g_k[MTOT*DMODEL];
__device__ float g_v[MTOT*DMODEL];
__device__ float g_attn[MTOT*DMODEL];

// ============================================================
// SGEMM: C[M=4096, N=1024] = A[4096,1024] @ W[1024,1024] + bias
// 128x128 block tile, BK=16, 256 threads, 8x8 per thread (4+4 split)
// ============================================================
__device__ __forceinline__ void gemm_tile(const float* __restrict__ A,
                                          const float* __restrict__ W,
                                          const float* __restrict__ bias,
                                          float* __restrict__ C)
{
    __shared__ float As[16*128];   // transposed: As[k][m]
    __shared__ float Bs[16*128];   // Bs[k][n]

    const int tid = threadIdx.x;
    const int m0  = blockIdx.y * 128;
    const int n0  = blockIdx.x * 128;
    const int tx  = tid & 15;
    const int ty  = tid >> 4;

    float acc[8][8];
#pragma unroll
    for (int i = 0; i < 8; i++)
#pragma unroll
        for (int j = 0; j < 8; j++) acc[i][j] = 0.f;

    for (int k0 = 0; k0 < DMODEL; k0 += 16) {
        // load A tile 128x16 (transpose into As)
#pragma unroll
        for (int l = 0; l < 2; l++) {
            int idx = tid + l * 256;          // 0..511
            int row = idx >> 2, c4 = idx & 3;
            float4 a = *(const float4*)(A + (size_t)(m0 + row) * DMODEL + k0 + c4 * 4);
            As[(c4*4+0)*128 + row] = a.x;
            As[(c4*4+1)*128 + row] = a.y;
            As[(c4*4+2)*128 + row] = a.z;
            As[(c4*4+3)*128 + row] = a.w;
        }
        // load W tile 16x128
#pragma unroll
        for (int l = 0; l < 2; l++) {
            int idx = tid + l * 256;          // 0..511
            int row = idx >> 5, c4 = idx & 31;
            *(float4*)(Bs + row * 128 + c4 * 4) =
                *(const float4*)(W + (size_t)(k0 + row) * DMODEL + n0 + c4 * 4);
        }
        __syncthreads();

#pragma unroll
        for (int kk = 0; kk < 16; kk++) {
            float a[8], b[8];
            float4 t;
            t = *(float4*)(As + kk*128 + ty*4);       a[0]=t.x; a[1]=t.y; a[2]=t.z; a[3]=t.w;
            t = *(float4*)(As + kk*128 + 64 + ty*4);  a[4]=t.x; a[5]=t.y; a[6]=t.z; a[7]=t.w;
            t = *(float4*)(Bs + kk*128 + tx*4);       b[0]=t.x; b[1]=t.y; b[2]=t.z; b[3]=t.w;
            t = *(float4*)(Bs + kk*128 + 64 + tx*4);  b[4]=t.x; b[5]=t.y; b[6]=t.z; b[7]=t.w;
#pragma unroll
            for (int i = 0; i < 8; i++)
#pragma unroll
                for (int j = 0; j < 8; j++)
                    acc[i][j] = fmaf(a[i], b[j], acc[i][j]);
        }
        __syncthreads();
    }

    // epilogue: rows {m0+half*64+ty*4+i}, cols {n0+ch*64+tx*4+j}
#pragma unroll
    for (int half = 0; half < 2; half++) {
#pragma unroll
        for (int i = 0; i < 4; i++) {
            int row = m0 + half * 64 + ty * 4 + i;
#pragma unroll
            for (int ch = 0; ch < 2; ch++) {
                int col = n0 + ch * 64 + tx * 4;
                float4 o;
                o.x = acc[half*4+i][ch*4+0] + bias[col+0];
                o.y = acc[half*4+i][ch*4+1] + bias[col+1];
                o.z = acc[half*4+i][ch*4+2] + bias[col+2];
                o.w = acc[half*4+i][ch*4+3] + bias[col+3];
                *(float4*)(C + (size_t)row * DMODEL + col) = o;
            }
        }
    }
}

__global__ __launch_bounds__(256, 2) void qkv_gemm_kernel(
    const float* __restrict__ x,
    const float* __restrict__ Wq, const float* __restrict__ bq,
    const float* __restrict__ Wk, const float* __restrict__ bk,
    const float* __restrict__ Wv, const float* __restrict__ bv)
{
    if (blockIdx.z == 0)      gemm_tile(x, Wq, bq, g_q);
    else if (blockIdx.z == 1) gemm_tile(x, Wk, bk, g_k);
    else                      gemm_tile(x, Wv, bv, g_v);
}

__global__ __launch_bounds__(256, 2) void out_gemm_kernel(
    const float* __restrict__ Wo, const float* __restrict__ bo,
    float* __restrict__ out)
{
    gemm_tile(g_attn, Wo, bo, out);
}

// ============================================================
// Sliding-window attention.
// One block = (b, h, 32-query tile). Key band: [q0-64, q0+31+64] = 160 keys.
// ============================================================
#define QT      32
#define KT      160
#define QPITCH  68
#define KPITCH  68
#define SPITCH  161
#define ATTN_SMEM_FLOATS (QT*QPITCH + 2*KT*KPITCH + QT*SPITCH)
#define ATTN_SMEM_BYTES  (ATTN_SMEM_FLOATS * 4)

__global__ __launch_bounds__(128) void attn_kernel()
{
    extern __shared__ float sm[];
    float* Qs = sm;                     // [32][68]
    float* Ks = Qs + QT * QPITCH;       // [160][68]
    float* Vs = Ks + KT * KPITCH;       // [160][68]
    float* Sc = Vs + KT * KPITCH;       // [32][161]

    const int b  = blockIdx.z;
    const int h  = blockIdx.y;
    const int q0 = blockIdx.x * QT;
    const int tid = threadIdx.x;
    const int kbase = q0 - WIN;

    // ---- load Q tile (32 x 64) ----
    for (int l = tid; l < QT * 16; l += 128) {
        int r = l >> 4, c4 = (l & 15) * 4;
        float4 v = *(const float4*)(g_q + ((size_t)(b * SEQ + q0 + r)) * DMODEL + h * HDIM + c4);
        *(float4*)(Qs + r * QPITCH + c4) = v;
    }
    // ---- load K/V band (160 x 64), zero-fill out-of-range rows ----
    for (int l = tid; l < KT * 16; l += 128) {
        int r = l >> 4, c4 = (l & 15) * 4;
        int kg = kbase + r;
        float4 kv = make_float4(0.f, 0.f, 0.f, 0.f);
        float4 vv = make_float4(0.f, 0.f, 0.f, 0.f);
        if (kg >= 0 && kg < SEQ) {
            size_t off = ((size_t)(b * SEQ + kg)) * DMODEL + h * HDIM + c4;
            kv = *(const float4*)(g_k + off);
            vv = *(const float4*)(g_v + off);
        }
        *(float4*)(Ks + r * KPITCH + c4) = kv;
        *(float4*)(Vs + r * KPITCH + c4) = vv;
    }
    __syncthreads();

    // ---- scores: S[32][160] = Q @ K^T * scale, masked ----
    {
        const int txk = tid & 15;     // key lane; keys r = u*16 + txk
        const int tyq = tid >> 4;     // query group: queries tyq*4 + i
        float acc[4][10];
#pragma unroll
        for (int i = 0; i < 4; i++)
#pragma unroll
            for (int u = 0; u < 10; u++) acc[i][u] = 0.f;

        for (int d = 0; d < HDIM; d++) {
            float qr[4];
#pragma unroll
            for (int i = 0; i < 4; i++) qr[i] = Qs[(tyq*4 + i) * QPITCH + d];
            float kr[10];
#pragma unroll
            for (int u = 0; u < 10; u++) kr[u] = Ks[(u*16 + txk) * KPITCH + d];
#pragma unroll
            for (int i = 0; i < 4; i++)
#pragma unroll
                for (int u = 0; u < 10; u++)
                    acc[i][u] = fmaf(qr[i], kr[u], acc[i][u]);
        }

        const float scale = 0.125f;   // 1/sqrt(64)
#pragma unroll
        for (int i = 0; i < 4; i++) {
            int q  = tyq * 4 + i;
            int qg = q0 + q;
#pragma unroll
            for (int u = 0; u < 10; u++) {
                int r  = u * 16 + txk;
                int kg = kbase + r;
                int dist = qg - kg;
                bool ok = (kg >= 0) && (kg < SEQ) && (dist <= WIN) && (dist >= -WIN);
                Sc[q * SPITCH + r] = ok ? acc[i][u] * scale : -1e30f;
            }
        }
    }
    __syncthreads();

    // ---- softmax over each row of 160 (4 threads per query) ----
    {
        const int q = tid >> 2;       // 0..31
        const int j = tid & 3;        // group lane; lanes q*4+j are contiguous
        float* row = Sc + q * SPITCH + j * 40;
        float m = -1e30f;
#pragma unroll 8
        for (int t = 0; t < 40; t++) m = fmaxf(m, row[t]);
        m = fmaxf(m, __shfl_xor_sync(0xffffffffu, m, 1));
        m = fmaxf(m, __shfl_xor_sync(0xffffffffu, m, 2));
        float s = 0.f;
#pragma unroll 8
        for (int t = 0; t < 40; t++) {
            float e = __expf(row[t] - m);
            row[t] = e;
            s += e;
        }
        s += __shfl_xor_sync(0xffffffffu, s, 1);
        s += __shfl_xor_sync(0xffffffffu, s, 2);
        float inv = 1.f / s;
#pragma unroll 8
        for (int t = 0; t < 40; t++) row[t] *= inv;
    }
    __syncthreads();

    // ---- out = P[32][160] @ V[160][64] ----
    {
        const int dx = tid & 15;      // 4 output dims: dx*4..dx*4+3
        const int qy = tid >> 4;      // 4 queries: qy*4..qy*4+3
        float acc[4][4];
#pragma unroll
        for (int i = 0; i < 4; i++)
#pragma unroll
            for (int j = 0; j < 4; j++) acc[i][j] = 0.f;

        for (int r = 0; r < KT; r++) {
            float p[4];
#pragma unroll
            for (int i = 0; i < 4; i++) p[i] = Sc[(qy*4 + i) * SPITCH + r];
            float4 v = *(float4*)(Vs + r * KPITCH + dx * 4);
#pragma unroll
            for (int i = 0; i < 4; i++) {
                acc[i][0] = fmaf(p[i], v.x, acc[i][0]);
                acc[i][1] = fmaf(p[i], v.y, acc[i][1]);
                acc[i][2] = fmaf(p[i], v.z, acc[i][2]);
                acc[i][3] = fmaf(p[i], v.w, acc[i][3]);
            }
        }
#pragma unroll
        for (int i = 0; i < 4; i++) {
            float4 o;
            o.x = acc[i][0]; o.y = acc[i][1]; o.z = acc[i][2]; o.w = acc[i][3];
            *(float4*)(g_attn + ((size_t)(b * SEQ + q0 + qy*4 + i)) * DMODEL + h * HDIM + dx * 4) = o;
        }
    }
}

// ============================================================
extern "C" void kernel_launch(void* const* d_in, const int* in_sizes, int n_in,
                              void* d_out, int out_size)
{
    const float* x  = (const float*)d_in[0];
    const float* Wq = (const float*)d_in[1];
    const float* bq = (const float*)d_in[2];
    const float* Wk = (const float*)d_in[3];
    const float* bk = (const float*)d_in[4];
    const float* Wv = (const float*)d_in[5];
    const float* bv = (const float*)d_in[6];
    const float* Wo = (const float*)d_in[7];
    const float* bo = (const float*)d_in[8];
    float* out = (float*)d_out;

    cudaFuncSetAttribute(attn_kernel,
                         cudaFuncAttributeMaxDynamicSharedMemorySize,
                         ATTN_SMEM_BYTES);

    dim3 gq(DMODEL / 128, MTOT / 128, 3);       // 8 x 32 x 3
    qkv_gemm_kernel<<<gq, 256>>>(x, Wq, bq, Wk, bk, Wv, bv);

    dim3 ga(SEQ / QT, NHEADS, BATCH);           // 64 x 16 x 2
    attn_kernel<<<ga, 128, ATTN_SMEM_BYTES>>>();

    dim3 go(DMODEL / 128, MTOT / 128, 1);       // 8 x 32
    out_gemm_kernel<<<go, 256>>>(Wo, bo, out);
}

// round 3
// speedup vs baseline: 1.7562x; 1.7562x over previous
#include <cuda_runtime.h>
#include <cuda_bf16.h>
#include <math.h>
#include <stdint.h>

#define BATCH   2
#define SEQ     2048
#define DMODEL  1024
#define NHEADS  16
#define HDIM    64
#define WIN     64
#define MTOT    (BATCH*SEQ)   // 4096
#define WSZ     (DMODEL*DMODEL)

// ---------------- scratch (static device globals) ----------------
__device__ __nv_bfloat16 g_xh[MTOT*DMODEL];
__device__ __nv_bfloat16 g_xl[MTOT*DMODEL];
__device__ __nv_bfloat16 g_wh[4*WSZ];   // transposed [n][k], bf16 hi
__device__ __nv_bfloat16 g_wl[4*WSZ];   // transposed [n][k], bf16 lo
__device__ float g_q[MTOT*DMODEL];
__device__ float g_k[MTOT*DMODEL];
__device__ float g_v[MTOT*DMODEL];
__device__ __nv_bfloat16 g_ah[MTOT*DMODEL];  // attention out, bf16 hi
__device__ __nv_bfloat16 g_al[MTOT*DMODEL];  // attention out, bf16 lo

// ---------------- PTX helpers (non-'a' features only) ----------------
__device__ __forceinline__ uint32_t smem_u32(const void* p) {
    uint32_t a;
    asm("{ .reg .u64 t; cvta.to.shared.u64 t, %1; cvt.u32.u64 %0, t; }" : "=r"(a) : "l"(p));
    return a;
}
__device__ __forceinline__ void cp_async16(uint32_t s, const void* g) {
    asm volatile("cp.async.cg.shared.global [%0], [%1], 16;" :: "r"(s), "l"(g));
}
#define CP_COMMIT() asm volatile("cp.async.commit_group;" ::: "memory")
#define CP_WAIT(n)  asm volatile("cp.async.wait_group %0;" :: "n"(n) : "memory")

__device__ __forceinline__ void ldsm_x4(uint32_t* r, uint32_t a) {
    asm volatile("ldmatrix.sync.aligned.m8n8.x4.shared.b16 {%0,%1,%2,%3}, [%4];"
        : "=r"(r[0]), "=r"(r[1]), "=r"(r[2]), "=r"(r[3]) : "r"(a));
}
__device__ __forceinline__ void ldsm_x2(uint32_t* r, uint32_t a) {
    asm volatile("ldmatrix.sync.aligned.m8n8.x2.shared.b16 {%0,%1}, [%2];"
        : "=r"(r[0]), "=r"(r[1]) : "r"(a));
}
__device__ __forceinline__ void mma_bf16(float* d, const uint32_t* a, const uint32_t* b) {
    asm volatile(
        "mma.sync.aligned.m16n8k16.row.col.f32.bf16.bf16.f32 "
        "{%0,%1,%2,%3}, {%4,%5,%6,%7}, {%8,%9}, {%0,%1,%2,%3};"
        : "+f"(d[0]), "+f"(d[1]), "+f"(d[2]), "+f"(d[3])
        : "r"(a[0]), "r"(a[1]), "r"(a[2]), "r"(a[3]), "r"(b[0]), "r"(b[1]));
}

// ============================================================
// Conversion kernels
// ============================================================
__global__ __launch_bounds__(256) void convert_x_kernel(const float* __restrict__ x)
{
    int row = blockIdx.x;
    int i = threadIdx.x * 4;
    size_t off = (size_t)row * DMODEL + i;
    float4 v = *(const float4*)(x + off);
    __nv_bfloat162 h01, h23, l01, l23;
    h01.x = __float2bfloat16(v.x); l01.x = __float2bfloat16(v.x - __bfloat162float(h01.x));
    h01.y = __float2bfloat16(v.y); l01.y = __float2bfloat16(v.y - __bfloat162float(h01.y));
    h23.x = __float2bfloat16(v.z); l23.x = __float2bfloat16(v.z - __bfloat162float(h23.x));
    h23.y = __float2bfloat16(v.w); l23.y = __float2bfloat16(v.w - __bfloat162float(h23.y));
    *(__nv_bfloat162*)(g_xh + off) = h01; *(__nv_bfloat162*)(g_xh + off + 2) = h23;
    *(__nv_bfloat162*)(g_xl + off) = l01; *(__nv_bfloat162*)(g_xl + off + 2) = l23;
}

// transpose W[k][n] -> Wt[n][k], split hi/lo. block (32,8), tile 32x32
__global__ __launch_bounds__(256) void transpose_w_kernel(
    const float* __restrict__ Wq, const float* __restrict__ Wk,
    const float* __restrict__ Wv, const float* __restrict__ Wo)
{
    __shared__ float tile[32][33];
    int z = blockIdx.z;
    const float* W = (z == 0) ? Wq : (z == 1) ? Wk : (z == 2) ? Wv : Wo;
    __nv_bfloat16* Th = g_wh + (size_t)z * WSZ;
    __nv_bfloat16* Tl = g_wl + (size_t)z * WSZ;
    int kb = blockIdx.y * 32, nb = blockIdx.x * 32;
    int tx = threadIdx.x, ty = threadIdx.y;
#pragma unroll
    for (int i = 0; i < 4; i++)
        tile[ty + 8 * i][tx] = W[(size_t)(kb + ty + 8 * i) * DMODEL + nb + tx];
    __syncthreads();
#pragma unroll
    for (int i = 0; i < 4; i++) {
        float v = tile[tx][ty + 8 * i];
        __nv_bfloat16 h = __float2bfloat16(v);
        __nv_bfloat16 l = __float2bfloat16(v - __bfloat162float(h));
        size_t o = (size_t)(nb + ty + 8 * i) * DMODEL + kb + tx;
        Th[o] = h; Tl[o] = l;
    }
}

// ============================================================
// Split-bf16 HMMA GEMM (mma.sync m16n8k16): C = A @ B^T + bias
// A: [M][K] bf16 hi/lo, B: [N][K] bf16 hi/lo (transposed weights)
// CTA tile 128x128, BK=32, 8 warps (2x4), warp tile 64x32.
// cp.async double-buffered, SMEM pitch 40 bf16 (80 B) -> conflict-free ldmatrix.
// ============================================================
#define BK       32
#define PITCHE   40                    // bf16 elements per SMEM row
#define PITCHB   (PITCHE*2)            // 80 bytes
#define MAT_B    (128*PITCHB)          // 10240 B per matrix tile
#define STAGE_B2 (4*MAT_B)             // 40960 B per stage
#define GEMM_SMEM (2*STAGE_B2)         // 81920 B
#define ROW64B   (64*PITCHB)           // 5120

__global__ __launch_bounds__(256) void hmma_gemm_kernel(
    int mode, const float* __restrict__ b0, const float* __restrict__ b1,
    const float* __restrict__ b2, float* __restrict__ outp)
{
    extern __shared__ char sm[];
    const uint32_t sbase = smem_u32(sm);

    const int tid  = threadIdx.x;
    const int lane = tid & 31;
    const int wid  = tid >> 5;
    const int wm   = wid >> 2;      // 0..1
    const int wn   = wid & 3;       // 0..3
    const int m0   = blockIdx.y * 128;
    const int n0   = blockIdx.x * 128;

    const __nv_bfloat16 *Ah, *Al, *Bh, *Bl;
    const float* bias;
    float* C;
    if (mode == 0) {
        int z = blockIdx.z;
        Ah = g_xh; Al = g_xl;
        Bh = g_wh + (size_t)z * WSZ; Bl = g_wl + (size_t)z * WSZ;
        bias = (z == 0) ? b0 : (z == 1) ? b1 : b2;
        C = (z == 0) ? g_q : (z == 1) ? g_k : g_v;
    } else {
        Ah = g_ah; Al = g_al;
        Bh = g_wh + 3ull * WSZ; Bl = g_wl + 3ull * WSZ;
        bias = b0; C = outp;
    }

    // ---- cp.async per-thread geometry ----
    const int rowA = tid >> 2;          // 0..63
    const int seg  = tid & 3;           // 16B segment within 32-elem row chunk
    const uint32_t s0 = (uint32_t)rowA * PITCHB + (uint32_t)seg * 16;
    const __nv_bfloat16* pAh = Ah + (size_t)(m0 + rowA) * DMODEL + seg * 8;
    const __nv_bfloat16* pAl = Al + (size_t)(m0 + rowA) * DMODEL + seg * 8;
    const __nv_bfloat16* pBh = Bh + (size_t)(n0 + rowA) * DMODEL + seg * 8;
    const __nv_bfloat16* pBl = Bl + (size_t)(n0 + rowA) * DMODEL + seg * 8;

#define PREFETCH(stage, cc) do {                                             \
    const int _k0 = (cc) * BK;                                               \
    const uint32_t _sb = sbase + (uint32_t)(stage) * STAGE_B2 + s0;          \
    cp_async16(_sb,                      pAh + _k0);                         \
    cp_async16(_sb + ROW64B,             pAh + 64 * DMODEL + _k0);           \
    cp_async16(_sb + MAT_B,              pAl + _k0);                         \
    cp_async16(_sb + MAT_B + ROW64B,     pAl + 64 * DMODEL + _k0);           \
    cp_async16(_sb + 2 * MAT_B,          pBh + _k0);                         \
    cp_async16(_sb + 2 * MAT_B + ROW64B, pBh + 64 * DMODEL + _k0);           \
    cp_async16(_sb + 3 * MAT_B,          pBl + _k0);                         \
    cp_async16(_sb + 3 * MAT_B + ROW64B, pBl + 64 * DMODEL + _k0);           \
} while (0)

    float acc[4][4][4];
#pragma unroll
    for (int i = 0; i < 4; i++)
#pragma unroll
        for (int j = 0; j < 4; j++)
#pragma unroll
            for (int e = 0; e < 4; e++) acc[i][j][e] = 0.f;

    // ldmatrix per-lane address components
    const int arow_l = ((lane >> 3) & 1) * 8 + (lane & 7);
    const int akoff  = (lane >> 4) * 8;            // k offset by matrix pair
    const int brow_l = lane & 7;
    const int bkoff  = ((lane >> 3) & 1) * 8;

    PREFETCH(0, 0);
    CP_COMMIT();

    const int NCHUNK = DMODEL / BK;   // 32
    for (int c = 0; c < NCHUNK; c++) {
        const int s = c & 1;
        if (c < NCHUNK - 1) { PREFETCH(s ^ 1, c + 1); CP_COMMIT(); CP_WAIT(1); }
        else                { CP_WAIT(0); }
        __syncthreads();

        const uint32_t stb = sbase + (uint32_t)s * STAGE_B2;
#pragma unroll
        for (int ks = 0; ks < 2; ks++) {
            uint32_t ah[4][4], al[4][4], bh[4][2], bl[4][2];
#pragma unroll
            for (int mt = 0; mt < 4; mt++) {
                uint32_t ad = stb + (uint32_t)(wm * 64 + mt * 16 + arow_l) * PITCHB
                                  + (uint32_t)(ks * 16 + akoff) * 2;
                ldsm_x4(ah[mt], ad);
                ldsm_x4(al[mt], ad + MAT_B);
            }
#pragma unroll
            for (int nt = 0; nt < 4; nt++) {
                uint32_t bd = stb + 2 * MAT_B
                                  + (uint32_t)(wn * 32 + nt * 8 + brow_l) * PITCHB
                                  + (uint32_t)(ks * 16 + bkoff) * 2;
                ldsm_x2(bh[nt], bd);
                ldsm_x2(bl[nt], bd + MAT_B);
            }
#pragma unroll
            for (int mt = 0; mt < 4; mt++)
#pragma unroll
                for (int nt = 0; nt < 4; nt++) {
                    mma_bf16(acc[mt][nt], ah[mt], bh[nt]);
                    mma_bf16(acc[mt][nt], ah[mt], bl[nt]);
                    mma_bf16(acc[mt][nt], al[mt], bh[nt]);
                }
        }
        __syncthreads();
    }

    // ---- epilogue: accum layout m16n8 -> thread (g=lane>>2, pair=(lane&3)*2) ----
    const int g     = lane >> 2;
    const int cpair = (lane & 3) * 2;
#pragma unroll
    for (int mt = 0; mt < 4; mt++) {
        int row0 = m0 + wm * 64 + mt * 16 + g;
#pragma unroll
        for (int nt = 0; nt < 4; nt++) {
            int col = n0 + wn * 32 + nt * 8 + cpair;
            float bx = bias[col], by = bias[col + 1];
            *(float2*)(C + (size_t)row0 * DMODEL + col) =
                make_float2(acc[mt][nt][0] + bx, acc[mt][nt][1] + by);
            *(float2*)(C + (size_t)(row0 + 8) * DMODEL + col) =
                make_float2(acc[mt][nt][2] + bx, acc[mt][nt][3] + by);
        }
    }
#undef PREFETCH
}

// ============================================================
// Sliding-window attention (fp32 compute, bf16 hi/lo output)
// ============================================================
#define QT      32
#define KT      160
#define QPITCH  68
#define KPITCH  68
#define SPITCH  161
#define ATTN_SMEM_FLOATS (QT*QPITCH + 2*KT*KPITCH + QT*SPITCH)
#define ATTN_SMEM_BYTES  (ATTN_SMEM_FLOATS * 4)

__global__ __launch_bounds__(128) void attn_kernel()
{
    extern __shared__ float smf[];
    float* Qs = smf;
    float* Ks = Qs + QT * QPITCH;
    float* Vs = Ks + KT * KPITCH;
    float* Sc = Vs + KT * KPITCH;

    const int b  = blockIdx.z;
    const int hh = blockIdx.y;
    const int q0 = blockIdx.x * QT;
    const int tid = threadIdx.x;
    const int kbase = q0 - WIN;

    for (int l = tid; l < QT * 16; l += 128) {
        int r = l >> 4, c4 = (l & 15) * 4;
        float4 v = *(const float4*)(g_q + ((size_t)(b * SEQ + q0 + r)) * DMODEL + hh * HDIM + c4);
        *(float4*)(Qs + r * QPITCH + c4) = v;
    }
    for (int l = tid; l < KT * 16; l += 128) {
        int r = l >> 4, c4 = (l & 15) * 4;
        int kg = kbase + r;
        float4 kv = make_float4(0.f, 0.f, 0.f, 0.f);
        float4 vv = make_float4(0.f, 0.f, 0.f, 0.f);
        if (kg >= 0 && kg < SEQ) {
            size_t off = ((size_t)(b * SEQ + kg)) * DMODEL + hh * HDIM + c4;
            kv = *(const float4*)(g_k + off);
            vv = *(const float4*)(g_v + off);
        }
        *(float4*)(Ks + r * KPITCH + c4) = kv;
        *(float4*)(Vs + r * KPITCH + c4) = vv;
    }
    __syncthreads();

    {
        const int txk = tid & 15;
        const int tyq = tid >> 4;
        float acc[4][10];
#pragma unroll
        for (int i = 0; i < 4; i++)
#pragma unroll
            for (int u = 0; u < 10; u++) acc[i][u] = 0.f;
        for (int d = 0; d < HDIM; d++) {
            float qr[4];
#pragma unroll
            for (int i = 0; i < 4; i++) qr[i] = Qs[(tyq * 4 + i) * QPITCH + d];
            float kr[10];
#pragma unroll
            for (int u = 0; u < 10; u++) kr[u] = Ks[(u * 16 + txk) * KPITCH + d];
#pragma unroll
            for (int i = 0; i < 4; i++)
#pragma unroll
                for (int u = 0; u < 10; u++)
                    acc[i][u] = fmaf(qr[i], kr[u], acc[i][u]);
        }
        const float scale = 0.125f;
#pragma unroll
        for (int i = 0; i < 4; i++) {
            int q  = tyq * 4 + i;
            int qg = q0 + q;
#pragma unroll
            for (int u = 0; u < 10; u++) {
                int r  = u * 16 + txk;
                int kg = kbase + r;
                int dist = qg - kg;
                bool ok = (kg >= 0) && (kg < SEQ) && (dist <= WIN) && (dist >= -WIN);
                Sc[q * SPITCH + r] = ok ? acc[i][u] * scale : -1e30f;
            }
        }
    }
    __syncthreads();

    {
        const int q = tid >> 2;
        const int j = tid & 3;
        float* row = Sc + q * SPITCH + j * 40;
        float m = -1e30f;
#pragma unroll 8
        for (int t = 0; t < 40; t++) m = fmaxf(m, row[t]);
        m = fmaxf(m, __shfl_xor_sync(0xffffffffu, m, 1));
        m = fmaxf(m, __shfl_xor_sync(0xffffffffu, m, 2));
        float s = 0.f;
#pragma unroll 8
        for (int t = 0; t < 40; t++) { float e = __expf(row[t] - m); row[t] = e; s += e; }
        s += __shfl_xor_sync(0xffffffffu, s, 1);
        s += __shfl_xor_sync(0xffffffffu, s, 2);
        float inv = 1.f / s;
#pragma unroll 8
        for (int t = 0; t < 40; t++) row[t] *= inv;
    }
    __syncthreads();

    {
        const int dx = tid & 15;
        const int qy = tid >> 4;
        float acc[4][4];
#pragma unroll
        for (int i = 0; i < 4; i++)
#pragma unroll
            for (int j = 0; j < 4; j++) acc[i][j] = 0.f;
        for (int r = 0; r < KT; r++) {
            float p[4];
#pragma unroll
            for (int i = 0; i < 4; i++) p[i] = Sc[(qy * 4 + i) * SPITCH + r];
            float4 v = *(float4*)(Vs + r * KPITCH + dx * 4);
#pragma unroll
            for (int i = 0; i < 4; i++) {
                acc[i][0] = fmaf(p[i], v.x, acc[i][0]);
                acc[i][1] = fmaf(p[i], v.y, acc[i][1]);
                acc[i][2] = fmaf(p[i], v.z, acc[i][2]);
                acc[i][3] = fmaf(p[i], v.w, acc[i][3]);
            }
        }
#pragma unroll
        for (int i = 0; i < 4; i++) {
            size_t off = ((size_t)(b * SEQ + q0 + qy * 4 + i)) * DMODEL + hh * HDIM + dx * 4;
            __nv_bfloat162 h01, h23, l01, l23;
            h01.x = __float2bfloat16(acc[i][0]); l01.x = __float2bfloat16(acc[i][0] - __bfloat162float(h01.x));
            h01.y = __float2bfloat16(acc[i][1]); l01.y = __float2bfloat16(acc[i][1] - __bfloat162float(h01.y));
            h23.x = __float2bfloat16(acc[i][2]); l23.x = __float2bfloat16(acc[i][2] - __bfloat162float(h23.x));
            h23.y = __float2bfloat16(acc[i][3]); l23.y = __float2bfloat16(acc[i][3] - __bfloat162float(h23.y));
            *(__nv_bfloat162*)(g_ah + off) = h01; *(__nv_bfloat162*)(g_ah + off + 2) = h23;
            *(__nv_bfloat162*)(g_al + off) = l01; *(__nv_bfloat162*)(g_al + off + 2) = l23;
        }
    }
}

// ============================================================
extern "C" void kernel_launch(void* const* d_in, const int* in_sizes, int n_in,
                              void* d_out, int out_size)
{
    const float* x  = (const float*)d_in[0];
    const float* Wq = (const float*)d_in[1];
    const float* bq = (const float*)d_in[2];
    const float* Wk = (const float*)d_in[3];
    const float* bk = (const float*)d_in[4];
    const float* Wv = (const float*)d_in[5];
    const float* bv = (const float*)d_in[6];
    const float* Wo = (const float*)d_in[7];
    const float* bo = (const float*)d_in[8];
    float* out = (float*)d_out;

    cudaFuncSetAttribute(attn_kernel, cudaFuncAttributeMaxDynamicSharedMemorySize, ATTN_SMEM_BYTES);
    cudaFuncSetAttribute(hmma_gemm_kernel, cudaFuncAttributeMaxDynamicSharedMemorySize, GEMM_SMEM);

    convert_x_kernel<<<MTOT, 256>>>(x);
    transpose_w_kernel<<<dim3(32, 32, 4), dim3(32, 8)>>>(Wq, Wk, Wv, Wo);

    dim3 gq(DMODEL / 128, MTOT / 128, 3);
    hmma_gemm_kernel<<<gq, 256, GEMM_SMEM>>>(0, bq, bk, bv, nullptr);

    dim3 ga(SEQ / QT, NHEADS, BATCH);
    attn_kernel<<<ga, 128, ATTN_SMEM_BYTES>>>();

    dim3 go(DMODEL / 128, MTOT / 128, 1);
    hmma_gemm_kernel<<<go, 256, GEMM_SMEM>>>(1, bo, nullptr, nullptr, out);
}

// round 4
// speedup vs baseline: 2.5719x; 1.4645x over previous
#include <cuda_runtime.h>
#include <cuda_bf16.h>
#include <math.h>
#include <stdint.h>

#define BATCH   2
#define SEQ     2048
#define DMODEL  1024
#define NHEADS  16
#define HDIM    64
#define WIN     64
#define MTOT    (BATCH*SEQ)   // 4096
#define WSZ     (DMODEL*DMODEL)

// ---------------- scratch (static device globals) ----------------
__device__ __nv_bfloat16 g_xh[MTOT*DMODEL];
__device__ __nv_bfloat16 g_xl[MTOT*DMODEL];
__device__ __nv_bfloat16 g_wh[4*WSZ];   // transposed [n][k], bf16 hi
__device__ __nv_bfloat16 g_wl[4*WSZ];   // transposed [n][k], bf16 lo
__device__ __nv_bfloat16 g_qh[MTOT*DMODEL];
__device__ __nv_bfloat16 g_ql[MTOT*DMODEL];
__device__ __nv_bfloat16 g_kh[MTOT*DMODEL];
__device__ __nv_bfloat16 g_kl[MTOT*DMODEL];
__device__ __nv_bfloat16 g_vh[MTOT*DMODEL];
__device__ __nv_bfloat16 g_vl[MTOT*DMODEL];
__device__ __nv_bfloat16 g_ah[MTOT*DMODEL];  // attention out, bf16 hi
__device__ __nv_bfloat16 g_al[MTOT*DMODEL];  // attention out, bf16 lo

// ---------------- PTX helpers (non-'a' features only) ----------------
__device__ __forceinline__ uint32_t smem_u32(const void* p) {
    uint32_t a;
    asm("{ .reg .u64 t; cvta.to.shared.u64 t, %1; cvt.u32.u64 %0, t; }" : "=r"(a) : "l"(p));
    return a;
}
__device__ __forceinline__ void cp_async16(uint32_t s, const void* g) {
    asm volatile("cp.async.cg.shared.global [%0], [%1], 16;" :: "r"(s), "l"(g));
}
__device__ __forceinline__ void cp_async16z(uint32_t s, const void* g, uint32_t srcsz) {
    asm volatile("cp.async.cg.shared.global [%0], [%1], 16, %2;" :: "r"(s), "l"(g), "r"(srcsz));
}
#define CP_COMMIT() asm volatile("cp.async.commit_group;" ::: "memory")
#define CP_WAIT(n)  asm volatile("cp.async.wait_group %0;" :: "n"(n) : "memory")

__device__ __forceinline__ void ldsm_x4(uint32_t* r, uint32_t a) {
    asm volatile("ldmatrix.sync.aligned.m8n8.x4.shared.b16 {%0,%1,%2,%3}, [%4];"
        : "=r"(r[0]), "=r"(r[1]), "=r"(r[2]), "=r"(r[3]) : "r"(a));
}
__device__ __forceinline__ void ldsm_x2(uint32_t* r, uint32_t a) {
    asm volatile("ldmatrix.sync.aligned.m8n8.x2.shared.b16 {%0,%1}, [%2];"
        : "=r"(r[0]), "=r"(r[1]) : "r"(a));
}
__device__ __forceinline__ void ldsm_x2t(uint32_t* r, uint32_t a) {
    asm volatile("ldmatrix.sync.aligned.m8n8.x2.trans.shared.b16 {%0,%1}, [%2];"
        : "=r"(r[0]), "=r"(r[1]) : "r"(a));
}
__device__ __forceinline__ void mma_bf16(float* d, const uint32_t* a, const uint32_t* b) {
    asm volatile(
        "mma.sync.aligned.m16n8k16.row.col.f32.bf16.bf16.f32 "
        "{%0,%1,%2,%3}, {%4,%5,%6,%7}, {%8,%9}, {%0,%1,%2,%3};"
        : "+f"(d[0]), "+f"(d[1]), "+f"(d[2]), "+f"(d[3])
        : "r"(a[0]), "r"(a[1]), "r"(a[2]), "r"(a[3]), "r"(b[0]), "r"(b[1]));
}

__device__ __forceinline__ uint32_t pack_bf2(float x, float y) {
    __nv_bfloat162 h;
    h.x = __float2bfloat16(x); h.y = __float2bfloat16(y);
    return *(uint32_t*)&h;
}

// ============================================================
// Conversion kernels
// ============================================================
__global__ __launch_bounds__(256) void convert_x_kernel(const float* __restrict__ x)
{
    int row = blockIdx.x;
    int i = threadIdx.x * 4;
    size_t off = (size_t)row * DMODEL + i;
    float4 v = *(const float4*)(x + off);
    __nv_bfloat162 h01, h23, l01, l23;
    h01.x = __float2bfloat16(v.x); l01.x = __float2bfloat16(v.x - __bfloat162float(h01.x));
    h01.y = __float2bfloat16(v.y); l01.y = __float2bfloat16(v.y - __bfloat162float(h01.y));
    h23.x = __float2bfloat16(v.z); l23.x = __float2bfloat16(v.z - __bfloat162float(h23.x));
    h23.y = __float2bfloat16(v.w); l23.y = __float2bfloat16(v.w - __bfloat162float(h23.y));
    *(__nv_bfloat162*)(g_xh + off) = h01; *(__nv_bfloat162*)(g_xh + off + 2) = h23;
    *(__nv_bfloat162*)(g_xl + off) = l01; *(__nv_bfloat162*)(g_xl + off + 2) = l23;
}

// transpose W[k][n] -> Wt[n][k], split hi/lo. block (32,8), tile 32x32
__global__ __launch_bounds__(256) void transpose_w_kernel(
    const float* __restrict__ Wq, const float* __restrict__ Wk,
    const float* __restrict__ Wv, const float* __restrict__ Wo)
{
    __shared__ float tile[32][33];
    int z = blockIdx.z;
    const float* W = (z == 0) ? Wq : (z == 1) ? Wk : (z == 2) ? Wv : Wo;
    __nv_bfloat16* Th = g_wh + (size_t)z * WSZ;
    __nv_bfloat16* Tl = g_wl + (size_t)z * WSZ;
    int kb = blockIdx.y * 32, nb = blockIdx.x * 32;
    int tx = threadIdx.x, ty = threadIdx.y;
#pragma unroll
    for (int i = 0; i < 4; i++)
        tile[ty + 8 * i][tx] = W[(size_t)(kb + ty + 8 * i) * DMODEL + nb + tx];
    __syncthreads();
#pragma unroll
    for (int i = 0; i < 4; i++) {
        float v = tile[tx][ty + 8 * i];
        __nv_bfloat16 h = __float2bfloat16(v);
        __nv_bfloat16 l = __float2bfloat16(v - __bfloat162float(h));
        size_t o = (size_t)(nb + ty + 8 * i) * DMODEL + kb + tx;
        Th[o] = h; Tl[o] = l;
    }
}

// ============================================================
// Split-bf16 HMMA GEMM (mma.sync m16n8k16): C = A @ B^T + bias
// mode 0: writes bf16 hi/lo Q/K/V scratch.  mode 1: fp32 to outp.
// ============================================================
#define BK       32
#define PITCHE   40
#define PITCHB   (PITCHE*2)            // 80 bytes
#define MAT_B    (128*PITCHB)          // 10240 B
#define STAGE_B2 (4*MAT_B)             // 40960 B
#define GEMM_SMEM (2*STAGE_B2)         // 81920 B
#define ROW64B   (64*PITCHB)

__global__ __launch_bounds__(256) void hmma_gemm_kernel(
    int mode, const float* __restrict__ b0, const float* __restrict__ b1,
    const float* __restrict__ b2, float* __restrict__ outp)
{
    extern __shared__ char sm[];
    const uint32_t sbase = smem_u32(sm);

    const int tid  = threadIdx.x;
    const int lane = tid & 31;
    const int wid  = tid >> 5;
    const int wm   = wid >> 2;
    const int wn   = wid & 3;
    const int m0   = blockIdx.y * 128;
    const int n0   = blockIdx.x * 128;
    const int z    = blockIdx.z;

    const __nv_bfloat16 *Ah, *Al, *Bh, *Bl;
    const float* bias;
    if (mode == 0) {
        Ah = g_xh; Al = g_xl;
        Bh = g_wh + (size_t)z * WSZ; Bl = g_wl + (size_t)z * WSZ;
        bias = (z == 0) ? b0 : (z == 1) ? b1 : b2;
    } else {
        Ah = g_ah; Al = g_al;
        Bh = g_wh + 3ull * WSZ; Bl = g_wl + 3ull * WSZ;
        bias = b0;
    }

    const int rowA = tid >> 2;
    const int seg  = tid & 3;
    const uint32_t s0 = (uint32_t)rowA * PITCHB + (uint32_t)seg * 16;
    const __nv_bfloat16* pAh = Ah + (size_t)(m0 + rowA) * DMODEL + seg * 8;
    const __nv_bfloat16* pAl = Al + (size_t)(m0 + rowA) * DMODEL + seg * 8;
    const __nv_bfloat16* pBh = Bh + (size_t)(n0 + rowA) * DMODEL + seg * 8;
    const __nv_bfloat16* pBl = Bl + (size_t)(n0 + rowA) * DMODEL + seg * 8;

#define PREFETCH(stage, cc) do {                                             \
    const int _k0 = (cc) * BK;                                               \
    const uint32_t _sb = sbase + (uint32_t)(stage) * STAGE_B2 + s0;          \
    cp_async16(_sb,                      pAh + _k0);                         \
    cp_async16(_sb + ROW64B,             pAh + 64 * DMODEL + _k0);           \
    cp_async16(_sb + MAT_B,              pAl + _k0);                         \
    cp_async16(_sb + MAT_B + ROW64B,     pAl + 64 * DMODEL + _k0);           \
    cp_async16(_sb + 2 * MAT_B,          pBh + _k0);                         \
    cp_async16(_sb + 2 * MAT_B + ROW64B, pBh + 64 * DMODEL + _k0);           \
    cp_async16(_sb + 3 * MAT_B,          pBl + _k0);                         \
    cp_async16(_sb + 3 * MAT_B + ROW64B, pBl + 64 * DMODEL + _k0);           \
} while (0)

    float acc[4][4][4];
#pragma unroll
    for (int i = 0; i < 4; i++)
#pragma unroll
        for (int j = 0; j < 4; j++)
#pragma unroll
            for (int e = 0; e < 4; e++) acc[i][j][e] = 0.f;

    const int arow_l = ((lane >> 3) & 1) * 8 + (lane & 7);
    const int akoff  = (lane >> 4) * 8;
    const int brow_l = lane & 7;
    const int bkoff  = ((lane >> 3) & 1) * 8;

    PREFETCH(0, 0);
    CP_COMMIT();

    const int NCHUNK = DMODEL / BK;
    for (int c = 0; c < NCHUNK; c++) {
        const int s = c & 1;
        if (c < NCHUNK - 1) { PREFETCH(s ^ 1, c + 1); CP_COMMIT(); CP_WAIT(1); }
        else                { CP_WAIT(0); }
        __syncthreads();

        const uint32_t stb = sbase + (uint32_t)s * STAGE_B2;
#pragma unroll
        for (int ks = 0; ks < 2; ks++) {
            uint32_t ah[4][4], al[4][4], bh[4][2], bl[4][2];
#pragma unroll
            for (int mt = 0; mt < 4; mt++) {
                uint32_t ad = stb + (uint32_t)(wm * 64 + mt * 16 + arow_l) * PITCHB
                                  + (uint32_t)(ks * 16 + akoff) * 2;
                ldsm_x4(ah[mt], ad);
                ldsm_x4(al[mt], ad + MAT_B);
            }
#pragma unroll
            for (int nt = 0; nt < 4; nt++) {
                uint32_t bd = stb + 2 * MAT_B
                                  + (uint32_t)(wn * 32 + nt * 8 + brow_l) * PITCHB
                                  + (uint32_t)(ks * 16 + bkoff) * 2;
                ldsm_x2(bh[nt], bd);
                ldsm_x2(bl[nt], bd + MAT_B);
            }
#pragma unroll
            for (int mt = 0; mt < 4; mt++)
#pragma unroll
                for (int nt = 0; nt < 4; nt++) {
                    mma_bf16(acc[mt][nt], ah[mt], bh[nt]);
                    mma_bf16(acc[mt][nt], ah[mt], bl[nt]);
                    mma_bf16(acc[mt][nt], al[mt], bh[nt]);
                }
        }
        __syncthreads();
    }

    const int g     = lane >> 2;
    const int cpair = (lane & 3) * 2;
    if (mode == 0) {
        __nv_bfloat16* Ch = (z == 0) ? g_qh : (z == 1) ? g_kh : g_vh;
        __nv_bfloat16* Cl = (z == 0) ? g_ql : (z == 1) ? g_kl : g_vl;
#pragma unroll
        for (int mt = 0; mt < 4; mt++) {
            int row0 = m0 + wm * 64 + mt * 16 + g;
#pragma unroll
            for (int nt = 0; nt < 4; nt++) {
                int col = n0 + wn * 32 + nt * 8 + cpair;
                float bx = bias[col], by = bias[col + 1];
#pragma unroll
                for (int rr = 0; rr < 2; rr++) {
                    float o0 = acc[mt][nt][rr * 2 + 0] + bx;
                    float o1 = acc[mt][nt][rr * 2 + 1] + by;
                    __nv_bfloat162 h2, l2;
                    h2.x = __float2bfloat16(o0); l2.x = __float2bfloat16(o0 - __bfloat162float(h2.x));
                    h2.y = __float2bfloat16(o1); l2.y = __float2bfloat16(o1 - __bfloat162float(h2.y));
                    size_t off = (size_t)(row0 + rr * 8) * DMODEL + col;
                    *(__nv_bfloat162*)(Ch + off) = h2;
                    *(__nv_bfloat162*)(Cl + off) = l2;
                }
            }
        }
    } else {
        float* C = outp;
#pragma unroll
        for (int mt = 0; mt < 4; mt++) {
            int row0 = m0 + wm * 64 + mt * 16 + g;
#pragma unroll
            for (int nt = 0; nt < 4; nt++) {
                int col = n0 + wn * 32 + nt * 8 + cpair;
                float bx = bias[col], by = bias[col + 1];
                *(float2*)(C + (size_t)row0 * DMODEL + col) =
                    make_float2(acc[mt][nt][0] + bx, acc[mt][nt][1] + by);
                *(float2*)(C + (size_t)(row0 + 8) * DMODEL + col) =
                    make_float2(acc[mt][nt][2] + bx, acc[mt][nt][3] + by);
            }
        }
    }
#undef PREFETCH
}

// ============================================================
// Banded flash-attention with mma.sync (split bf16 hi/lo)
// CTA = (64 queries, head, batch); 4 warps; warp = 16 query rows.
// K band = 192 rows; per-warp valid band = 144 keys = 18 n-tiles.
// ============================================================
#define APITCH   72                 // bf16 elems per smem row
#define APITCHB  144
#define A_QH     0
#define A_QL     9216               // 64*144
#define A_KH     18432
#define A_KL     46080              // +192*144
#define A_VH     73728
#define A_VL     101376
#define ATTN_SMEM 129024

__global__ __launch_bounds__(128) void attn_mma_kernel()
{
    extern __shared__ char sm[];
    const uint32_t sb = smem_u32(sm);

    const int tid  = threadIdx.x;
    const int lane = tid & 31;
    const int w    = tid >> 5;
    const int b    = blockIdx.z;
    const int h    = blockIdx.y;
    const int q0   = blockIdx.x * 64;
    const int kbase = q0 - WIN;
    const size_t tok0 = (size_t)b * SEQ;
    const int coff = h * HDIM;

    // ---- async loads: group 0 = Q + K, group 1 = V ----
#pragma unroll
    for (int i = 0; i < 4; i++) {
        int task = tid + i * 128;          // 512 tasks
        int row = task >> 3, seg = task & 7;
        uint32_t d = sb + A_QH + (uint32_t)row * APITCHB + (uint32_t)seg * 16;
        size_t goff = (tok0 + q0 + row) * DMODEL + coff + seg * 8;
        cp_async16(d,                 g_qh + goff);
        cp_async16(d + (A_QL - A_QH), g_ql + goff);
    }
#pragma unroll
    for (int i = 0; i < 12; i++) {
        int task = tid + i * 128;          // 1536 tasks
        int row = task >> 3, seg = task & 7;
        int kg = kbase + row;
        int kgc = min(max(kg, 0), SEQ - 1);
        uint32_t sz = (kg >= 0 && kg < SEQ) ? 16u : 0u;
        uint32_t d = sb + A_KH + (uint32_t)row * APITCHB + (uint32_t)seg * 16;
        size_t goff = (tok0 + kgc) * DMODEL + coff + seg * 8;
        cp_async16z(d,                 g_kh + goff, sz);
        cp_async16z(d + (A_KL - A_KH), g_kl + goff, sz);
    }
    CP_COMMIT();
#pragma unroll
    for (int i = 0; i < 12; i++) {
        int task = tid + i * 128;
        int row = task >> 3, seg = task & 7;
        int kg = kbase + row;
        int kgc = min(max(kg, 0), SEQ - 1);
        uint32_t sz = (kg >= 0 && kg < SEQ) ? 16u : 0u;
        uint32_t d = sb + A_VH + (uint32_t)row * APITCHB + (uint32_t)seg * 16;
        size_t goff = (tok0 + kgc) * DMODEL + coff + seg * 8;
        cp_async16z(d,                 g_vh + goff, sz);
        cp_async16z(d + (A_VL - A_VH), g_vl + goff, sz);
    }
    CP_COMMIT();

    CP_WAIT(1);
    __syncthreads();

    // ---- Q fragments (per warp, rows w*16..w*16+15, 4 k-chunks) ----
    const int arow = w * 16 + ((lane >> 3) & 1) * 8 + (lane & 7);
    const int akoff = (lane >> 4) * 8;
    uint32_t qfh[4][4], qfl[4][4];
#pragma unroll
    for (int kc = 0; kc < 4; kc++) {
        uint32_t ad = sb + A_QH + (uint32_t)arow * APITCHB + (uint32_t)(kc * 16 + akoff) * 2;
        ldsm_x4(qfh[kc], ad);
        ldsm_x4(qfl[kc], ad + (A_QL - A_QH));
    }

    // ---- QK: S[16][144] in registers: 18 n-tiles ----
    float s[18][4];
#pragma unroll
    for (int t = 0; t < 18; t++)
#pragma unroll
        for (int e = 0; e < 4; e++) s[t][e] = 0.f;

    const int brow = lane & 7;
    const int bko  = ((lane >> 3) & 1) * 8;
#pragma unroll
    for (int t = 0; t < 18; t++) {
        int nt = 2 * w + t;
        uint32_t kb_addr = sb + A_KH + (uint32_t)(nt * 8 + brow) * APITCHB + (uint32_t)bko * 2;
#pragma unroll
        for (int kc = 0; kc < 4; kc++) {
            uint32_t kfh[2], kfl[2];
            uint32_t ka = kb_addr + (uint32_t)kc * 32;
            ldsm_x2(kfh, ka);
            ldsm_x2(kfl, ka + (A_KL - A_KH));
            mma_bf16(s[t], qfh[kc], kfh);
            mma_bf16(s[t], qfh[kc], kfl);
            mma_bf16(s[t], qfl[kc], kfh);
        }
    }

    // ---- mask + softmax (rows qg0 = q0+w*16+g and qg1 = qg0+8) ----
    const int g  = lane >> 2;
    const int c2 = (lane & 3) * 2;
    const int qg0 = q0 + w * 16 + g;
    const int qg1 = qg0 + 8;
    const float scale = 0.125f;

    float m0 = -1e30f, m1 = -1e30f;
#pragma unroll
    for (int t = 0; t < 18; t++) {
        int j0 = (2 * w + t) * 8 + c2;
        int kg0 = kbase + j0, kg1 = kg0 + 1;
        bool in0 = (kg0 >= 0) && (kg0 < SEQ);
        bool in1 = (kg1 >= 0) && (kg1 < SEQ);
        int d00 = kg0 - qg0, d10 = kg1 - qg0, d01 = kg0 - qg1, d11 = kg1 - qg1;
        s[t][0] = (in0 && d00 <= WIN && d00 >= -WIN) ? s[t][0] * scale : -1e30f;
        s[t][1] = (in1 && d10 <= WIN && d10 >= -WIN) ? s[t][1] * scale : -1e30f;
        s[t][2] = (in0 && d01 <= WIN && d01 >= -WIN) ? s[t][2] * scale : -1e30f;
        s[t][3] = (in1 && d11 <= WIN && d11 >= -WIN) ? s[t][3] * scale : -1e30f;
        m0 = fmaxf(m0, fmaxf(s[t][0], s[t][1]));
        m1 = fmaxf(m1, fmaxf(s[t][2], s[t][3]));
    }
    m0 = fmaxf(m0, __shfl_xor_sync(0xffffffffu, m0, 1));
    m0 = fmaxf(m0, __shfl_xor_sync(0xffffffffu, m0, 2));
    m1 = fmaxf(m1, __shfl_xor_sync(0xffffffffu, m1, 1));
    m1 = fmaxf(m1, __shfl_xor_sync(0xffffffffu, m1, 2));

    float r0 = 0.f, r1 = 0.f;
#pragma unroll
    for (int t = 0; t < 18; t++) {
        s[t][0] = __expf(s[t][0] - m0);
        s[t][1] = __expf(s[t][1] - m0);
        s[t][2] = __expf(s[t][2] - m1);
        s[t][3] = __expf(s[t][3] - m1);
        r0 += s[t][0] + s[t][1];
        r1 += s[t][2] + s[t][3];
    }
    r0 += __shfl_xor_sync(0xffffffffu, r0, 1);
    r0 += __shfl_xor_sync(0xffffffffu, r0, 2);
    r1 += __shfl_xor_sync(0xffffffffu, r1, 1);
    r1 += __shfl_xor_sync(0xffffffffu, r1, 2);
    float inv0 = 1.f / r0, inv1 = 1.f / r1;

    // ---- pack P into bf16 hi/lo A-fragments ----
    uint32_t ph01[18], ph23[18], pl01[18], pl23[18];
#pragma unroll
    for (int t = 0; t < 18; t++) {
        float p0 = s[t][0] * inv0, p1 = s[t][1] * inv0;
        float p2 = s[t][2] * inv1, p3 = s[t][3] * inv1;
        __nv_bfloat162 h2;
        h2.x = __float2bfloat16(p0); h2.y = __float2bfloat16(p1);
        ph01[t] = *(uint32_t*)&h2;
        pl01[t] = pack_bf2(p0 - __bfloat162float(h2.x), p1 - __bfloat162float(h2.y));
        h2.x = __float2bfloat16(p2); h2.y = __float2bfloat16(p3);
        ph23[t] = *(uint32_t*)&h2;
        pl23[t] = pack_bf2(p2 - __bfloat162float(h2.x), p3 - __bfloat162float(h2.y));
    }

    CP_WAIT(0);
    __syncthreads();

    // ---- PV: out[16][64] += P @ V, 9 k-chunks, 8 n-tiles ----
    float o[8][4];
#pragma unroll
    for (int nt = 0; nt < 8; nt++)
#pragma unroll
        for (int e = 0; e < 4; e++) o[nt][e] = 0.f;

    const int vrow_l = ((lane >> 3) & 1) * 8 + (lane & 7);
#pragma unroll
    for (int jl = 0; jl < 9; jl++) {
        uint32_t ah[4] = { ph01[2 * jl], ph23[2 * jl], ph01[2 * jl + 1], ph23[2 * jl + 1] };
        uint32_t al[4] = { pl01[2 * jl], pl23[2 * jl], pl01[2 * jl + 1], pl23[2 * jl + 1] };
        int keyb = (w + jl) * 16;
        uint32_t va_base = sb + A_VH + (uint32_t)(keyb + vrow_l) * APITCHB;
#pragma unroll
        for (int nt = 0; nt < 8; nt++) {
            uint32_t vfh[2], vfl[2];
            uint32_t va = va_base + (uint32_t)nt * 16;
            ldsm_x2t(vfh, va);
            ldsm_x2t(vfl, va + (A_VL - A_VH));
            mma_bf16(o[nt], ah, vfh);
            mma_bf16(o[nt], ah, vfl);
            mma_bf16(o[nt], al, vfh);
        }
    }

    // ---- store bf16 hi/lo for the output projection ----
    size_t row0 = tok0 + qg0;
    size_t row1 = tok0 + qg1;
#pragma unroll
    for (int nt = 0; nt < 8; nt++) {
        int col = coff + nt * 8 + c2;
        __nv_bfloat162 h2, l2;
        h2.x = __float2bfloat16(o[nt][0]); l2.x = __float2bfloat16(o[nt][0] - __bfloat162float(h2.x));
        h2.y = __float2bfloat16(o[nt][1]); l2.y = __float2bfloat16(o[nt][1] - __bfloat162float(h2.y));
        *(__nv_bfloat162*)(g_ah + row0 * DMODEL + col) = h2;
        *(__nv_bfloat162*)(g_al + row0 * DMODEL + col) = l2;
        h2.x = __float2bfloat16(o[nt][2]); l2.x = __float2bfloat16(o[nt][2] - __bfloat162float(h2.x));
        h2.y = __float2bfloat16(o[nt][3]); l2.y = __float2bfloat16(o[nt][3] - __bfloat162float(h2.y));
        *(__nv_bfloat162*)(g_ah + row1 * DMODEL + col) = h2;
        *(__nv_bfloat162*)(g_al + row1 * DMODEL + col) = l2;
    }
}

// ============================================================
extern "C" void kernel_launch(void* const* d_in, const int* in_sizes, int n_in,
                              void* d_out, int out_size)
{
    const float* x  = (const float*)d_in[0];
    const float* Wq = (const float*)d_in[1];
    const float* bq = (const float*)d_in[2];
    const float* Wk = (const float*)d_in[3];
    const float* bk = (const float*)d_in[4];
    const float* Wv = (const float*)d_in[5];
    const float* bv = (const float*)d_in[6];
    const float* Wo = (const float*)d_in[7];
    const float* bo = (const float*)d_in[8];
    float* out = (float*)d_out;

    cudaFuncSetAttribute(hmma_gemm_kernel, cudaFuncAttributeMaxDynamicSharedMemorySize, GEMM_SMEM);
    cudaFuncSetAttribute(attn_mma_kernel, cudaFuncAttributeMaxDynamicSharedMemorySize, ATTN_SMEM);

    convert_x_kernel<<<MTOT, 256>>>(x);
    transpose_w_kernel<<<dim3(32, 32, 4), dim3(32, 8)>>>(Wq, Wk, Wv, Wo);

    dim3 gq(DMODEL / 128, MTOT / 128, 3);
    hmma_gemm_kernel<<<gq, 256, GEMM_SMEM>>>(0, bq, bk, bv, nullptr);

    dim3 ga(SEQ / 64, NHEADS, BATCH);
    attn_mma_kernel<<<ga, 128, ATTN_SMEM>>>();

    dim3 go(DMODEL / 128, MTOT / 128, 1);
    hmma_gemm_kernel<<<go, 256, GEMM_SMEM>>>(1, bo, nullptr, nullptr, out);
}